// round 3
// baseline (speedup 1.0000x reference)
#include <cuda_runtime.h>

#define CCH    384
#define NHEADS 12
#define HD     32
#define FSZ    56
#define HWSZ   3136          // 56*56
#define BATCH  16
#define NTOK   (BATCH*HWSZ)  // 50176

// ---------------- scratch (device globals; no cudaMalloc allowed) ----------
__device__ float g_ybuf[CCH * NTOK];          //  77 MB: dwconv output, [c][b][hw]
__device__ float g_qkv [3 * CCH * NTOK];      // 231 MB: qkv, [ch][b][hw]
__device__ float g_attn[BATCH * CCH * HWSZ];  //  77 MB: attention output, NCHW

// ---------------------------------------------------------------------------
// Fused roll + depthwise 3x3 conv (pad 1), smem-tiled.
// input: NCHW. output: [c][b][hw] (K x N layout for the following GEMM).
// sh=3  implements roll(shift=-3) before conv; sh=53 implements roll(+3).
// One CTA per (b, c) plane: load rolled 56x56 plane to smem, conv from smem.
// ---------------------------------------------------------------------------
__global__ __launch_bounds__(256) void dwconv_kernel(
    const float* __restrict__ x, const float* __restrict__ wgt,
    float* __restrict__ y, int sh)
{
    __shared__ float sm[FSZ][FSZ + 1];
    int bc = blockIdx.x;           // b*CCH + c
    int b = bc / CCH, c = bc % CCH;
    float wt[9];
#pragma unroll
    for (int i = 0; i < 9; i++) wt[i] = __ldg(&wgt[c * 9 + i]);
    const float* xp = x + (size_t)bc * HWSZ;
    float*       yp = y + ((size_t)c * BATCH + b) * HWSZ;

    // load rolled plane: sm[h][w] = x[(h+sh)%56][(w+sh)%56]
    for (int hw = threadIdx.x; hw < HWSZ; hw += 256) {
        int h = hw / FSZ, w = hw - h * FSZ;
        int sr = h + sh; if (sr >= FSZ) sr -= FSZ;
        int sc = w + sh; if (sc >= FSZ) sc -= FSZ;
        sm[h][w] = __ldg(xp + sr * FSZ + sc);
    }
    __syncthreads();

    for (int hw = threadIdx.x; hw < HWSZ; hw += 256) {
        int h = hw / FSZ, w = hw - h * FSZ;
        float acc = 0.f;
#pragma unroll
        for (int i = 0; i < 3; i++) {
            int a = h - 1 + i;
            if (a < 0 || a >= FSZ) continue;
#pragma unroll
            for (int j = 0; j < 3; j++) {
                int bb = w - 1 + j;
                if (bb < 0 || bb >= FSZ) continue;
                acc += wt[i * 3 + j] * sm[a][bb];
            }
        }
        yp[hw] = acc;
    }
}

// ---------------------------------------------------------------------------
// SGEMM with fused bias, double-buffered smem.
// C[M,N] = A[M,K] @ B[K,N] + bias[M]
// BM=BN=128, BK=16, 256 threads, 8x8 per thread.
// M,N divisible by 128; K divisible by 16 (1152/384 x 50176 x 384 — exact).
// nchw=0: row-major [M][N] store.  nchw=1: scatter to NCHW (d_out).
// ---------------------------------------------------------------------------
#define BM 128
#define BN 128
#define BK 16
#define TM 8
#define TN 8

__global__ __launch_bounds__(256) void sgemm_bias(
    const float* __restrict__ A, const float* __restrict__ B,
    const float* __restrict__ bias, float* __restrict__ Cout,
    int M, int N, int K, int nchw)
{
    __shared__ float As[2][BK][BM];
    __shared__ float Bs[2][BK][BN];
    int tid = threadIdx.x;
    int bm = blockIdx.y * BM, bn = blockIdx.x * BN;
    int tx = (tid & 15) * TN;
    int ty = (tid >> 4) * TM;

    float acc[TM][TN];
#pragma unroll
    for (int i = 0; i < TM; i++)
#pragma unroll
        for (int j = 0; j < TN; j++) acc[i][j] = 0.f;

    // A: each thread loads 2 float4 (row arow, cols acol..acol+7 of the chunk)
    int arow = tid >> 1, acol = (tid & 1) * 8;
    // B: each thread loads 2 float4 (rows brow, brow+1, col bcol)
    int brow = (tid >> 5) * 2, bcol = (tid & 31) * 4;
    const float* Aptr = A + (size_t)(bm + arow) * K + acol;
    const float* Bptr = B + (size_t)brow * N + bn + bcol;

    // prologue: load chunk 0 into buffer 0
    float4 a0 = *(const float4*)(Aptr);
    float4 a1 = *(const float4*)(Aptr + 4);
    float4 b0 = *(const float4*)(Bptr);
    float4 b1 = *(const float4*)(Bptr + N);
    As[0][acol + 0][arow] = a0.x; As[0][acol + 1][arow] = a0.y;
    As[0][acol + 2][arow] = a0.z; As[0][acol + 3][arow] = a0.w;
    As[0][acol + 4][arow] = a1.x; As[0][acol + 5][arow] = a1.y;
    As[0][acol + 6][arow] = a1.z; As[0][acol + 7][arow] = a1.w;
    *(float4*)&Bs[0][brow][bcol]     = b0;
    *(float4*)&Bs[0][brow + 1][bcol] = b1;
    __syncthreads();

    int buf = 0;
    for (int k0 = 0; k0 < K; k0 += BK) {
        // issue loads for next chunk (if any) before computing current
        bool more = (k0 + BK) < K;
        if (more) {
            a0 = *(const float4*)(Aptr + k0 + BK);
            a1 = *(const float4*)(Aptr + k0 + BK + 4);
            b0 = *(const float4*)(Bptr + (size_t)(k0 + BK) * N);
            b1 = *(const float4*)(Bptr + (size_t)(k0 + BK + 1) * N);
        }
#pragma unroll
        for (int kk = 0; kk < BK; kk++) {
            float ar[TM], br[TN];
            *(float4*)&ar[0] = *(const float4*)&As[buf][kk][ty];
            *(float4*)&ar[4] = *(const float4*)&As[buf][kk][ty + 4];
            *(float4*)&br[0] = *(const float4*)&Bs[buf][kk][tx];
            *(float4*)&br[4] = *(const float4*)&Bs[buf][kk][tx + 4];
#pragma unroll
            for (int i = 0; i < TM; i++)
#pragma unroll
                for (int j = 0; j < TN; j++)
                    acc[i][j] += ar[i] * br[j];
        }
        if (more) {
            int nb = buf ^ 1;
            As[nb][acol + 0][arow] = a0.x; As[nb][acol + 1][arow] = a0.y;
            As[nb][acol + 2][arow] = a0.z; As[nb][acol + 3][arow] = a0.w;
            As[nb][acol + 4][arow] = a1.x; As[nb][acol + 5][arow] = a1.y;
            As[nb][acol + 6][arow] = a1.z; As[nb][acol + 7][arow] = a1.w;
            *(float4*)&Bs[nb][brow][bcol]     = b0;
            *(float4*)&Bs[nb][brow + 1][bcol] = b1;
            __syncthreads();
            buf = nb;
        }
    }

#pragma unroll
    for (int i = 0; i < TM; i++) {
        int m = bm + ty + i;
        float bv = bias[m];
#pragma unroll
        for (int j = 0; j < TN; j++) {
            int n = bn + tx + j;
            float v = acc[i][j] + bv;
            if (nchw) {
                int bidx = n / HWSZ, hw = n - bidx * HWSZ;
                Cout[((size_t)bidx * CCH + m) * HWSZ + hw] = v;
            } else {
                Cout[(size_t)m * N + n] = v;
            }
        }
    }
}

// ---------------------------------------------------------------------------
// Windowed attention: one CTA per (batch, head, window).
// 49 tokens x 32 dims; relative position bias + shift masks inline.
// qkv layout: [ch][b][hw] (row-major 1152 x 50176).
// output: NCHW (direct _from_windows scatter).
// bias[i,j] = pos_emb[xj-xi+6, yj-yi+6]   (rel = idx[j] - idx[i] + 6)
// ---------------------------------------------------------------------------
__global__ __launch_bounds__(256) void attn_kernel(
    const float* __restrict__ qkv, const float* __restrict__ pos_emb,
    float* __restrict__ out)
{
    const float DK = 0.17677669529663687f;  // 32^-0.5
    int blk = blockIdx.x;
    int wi = blk & 63;
    int head = (blk >> 6) % NHEADS;
    int b = blk / (64 * NHEADS);
    int wy = wi >> 3, wx = wi & 7;
    bool zm = (wy == 7);   // last window row -> zero_dim mask
    bool om = (wx == 7);   // last window col -> one_dim mask

    __shared__ float qs[49][33], ks[49][33], vs[49][33];
    __shared__ float dsh[49 * 49];
    __shared__ float pe[169];

    int tid = threadIdx.x;
    if (tid < 169) pe[tid] = pos_emb[tid];

    // load q/k/v tiles
    for (int t = tid; t < 49 * 32; t += 256) {
        int i = t >> 5, d = t & 31;
        int h = wy * 7 + i / 7, w = wx * 7 + i % 7;
        size_t base = (size_t)b * HWSZ + h * FSZ + w;
        int ch = head * HD + d;
        qs[i][d] = qkv[(size_t)ch * NTOK + base];
        ks[i][d] = qkv[(size_t)(ch + CCH) * NTOK + base];
        vs[i][d] = qkv[(size_t)(ch + 2 * CCH) * NTOK + base];
    }
    __syncthreads();

    // dots + bias + mask
    for (int t = tid; t < 49 * 49; t += 256) {
        int i = t / 49, j = t - i * 49;
        float s = 0.f;
#pragma unroll
        for (int d = 0; d < 32; d++) s += qs[i][d] * ks[j][d];
        s *= DK;
        int xi = i / 7, yi = i - (i / 7) * 7;
        int xj = j / 7, yj = j - (j / 7) * 7;
        s += pe[(xj - xi + 6) * 13 + (yj - yi + 6)];   // rel = idx[j]-idx[i]+6
        bool masked = (zm && ((i >= 28) != (j >= 28))) ||
                      (om && ((yi >= 4) != (yj >= 4)));
        dsh[t] = masked ? -1e30f : s;
    }
    __syncthreads();

    // row softmax (one thread per row)
    if (tid < 49) {
        float mx = -1e30f;
#pragma unroll
        for (int j = 0; j < 49; j++) mx = fmaxf(mx, dsh[tid * 49 + j]);
        float sum = 0.f;
#pragma unroll
        for (int j = 0; j < 49; j++) {
            float e = __expf(dsh[tid * 49 + j] - mx);
            dsh[tid * 49 + j] = e;
            sum += e;
        }
        float inv = 1.f / sum;
#pragma unroll
        for (int j = 0; j < 49; j++) dsh[tid * 49 + j] *= inv;
    }
    __syncthreads();

    // out = attn @ v, scattered straight to NCHW
    for (int t = tid; t < 49 * 32; t += 256) {
        int i = t >> 5, d = t & 31;
        float s = 0.f;
#pragma unroll
        for (int j = 0; j < 49; j++) s += dsh[i * 49 + j] * vs[j][d];
        int h = wy * 7 + i / 7, w = wx * 7 + i % 7;
        int ch = head * HD + d;
        out[((size_t)b * CCH + ch) * HWSZ + h * FSZ + w] = s;
    }
}

// ---------------------------------------------------------------------------
extern "C" void kernel_launch(void* const* d_in, const int* in_sizes, int n_in,
                              void* d_out, int out_size)
{
    const float* x       = (const float*)d_in[0];
    const float* qkv_dw  = (const float*)d_in[1];
    const float* qkv_pw  = (const float*)d_in[2];
    const float* qkv_pb  = (const float*)d_in[3];
    const float* out_dw  = (const float*)d_in[4];
    const float* out_pw  = (const float*)d_in[5];
    const float* out_pb  = (const float*)d_in[6];
    const float* pos_emb = (const float*)d_in[7];
    float* out = (float*)d_out;

    float* ybuf; cudaGetSymbolAddress((void**)&ybuf, g_ybuf);
    float* qkvb; cudaGetSymbolAddress((void**)&qkvb, g_qkv);
    float* attb; cudaGetSymbolAddress((void**)&attb, g_attn);

    // 1. roll(-3,-3) + dwconv3x3  -> [c][b][hw]
    dwconv_kernel<<<BATCH * CCH, 256>>>(x, qkv_dw, ybuf, 3);
    // 2. qkv pointwise: [1152,384] @ [384,50176] + bias
    sgemm_bias<<<dim3(NTOK / BN, 3 * CCH / BM), 256>>>(
        qkv_pw, ybuf, qkv_pb, qkvb, 3 * CCH, NTOK, CCH, 0);
    // 3. windowed attention -> NCHW
    attn_kernel<<<BATCH * NHEADS * 64, 256>>>(qkvb, pos_emb, attb);
    // 4. roll(+3,+3) + dwconv3x3 -> [c][b][hw]
    dwconv_kernel<<<BATCH * CCH, 256>>>(attb, out_dw, ybuf, 53);
    // 5. output pointwise: [384,384] @ [384,50176] + bias -> NCHW d_out
    sgemm_bias<<<dim3(NTOK / BN, CCH / BM), 256>>>(
        out_pw, ybuf, out_pb, out, CCH, NTOK, CCH, 1);
}

// round 5
// speedup vs baseline: 1.6773x; 1.6773x over previous
#include <cuda_runtime.h>
#include <cstdint>

#define CCH    384
#define NHEADS 12
#define HD     32
#define FSZ    56
#define HWSZ   3136          // 56*56
#define BATCH  16
#define NTOK   (BATCH*HWSZ)  // 50176

// ---------------- scratch (device globals; no cudaMalloc allowed) ----------
__device__ float g_ybuf[CCH * NTOK];          //  77 MB: dwconv output, [c][b][hw]
__device__ float g_qkv [3 * CCH * NTOK];      // 231 MB: qkv, [ch][b][hw]
__device__ float g_attn[BATCH * CCH * HWSZ];  //  77 MB: attention output, NCHW

__device__ __forceinline__ float to_tf32(float x) {
    float y;
    asm("cvt.rna.tf32.f32 %0, %1;" : "=f"(y) : "f"(x));
    return y;
}

// ---------------------------------------------------------------------------
// Fused roll + depthwise 3x3 conv (pad 1), smem-tiled, 224 threads (1 col/thr).
// input: NCHW. output: [c][b][hw].
// sh=3 implements roll(-3) before conv; sh=53 implements roll(+3).
// ---------------------------------------------------------------------------
__global__ __launch_bounds__(224) void dwconv_kernel(
    const float* __restrict__ x, const float* __restrict__ wgt,
    float* __restrict__ y, int sh)
{
    __shared__ float sm[FSZ][FSZ + 1];
    int bc = blockIdx.x;           // b*CCH + c
    int b = bc / CCH, c = bc % CCH;
    float wt[9];
#pragma unroll
    for (int i = 0; i < 9; i++) wt[i] = __ldg(&wgt[c * 9 + i]);
    const float* xp = x + (size_t)bc * HWSZ;
    float*       yp = y + ((size_t)c * BATCH + b) * HWSZ;

    int tid = threadIdx.x;
    int w = tid % FSZ, h0 = tid / FSZ;      // 224 = 4 rows x 56 cols
    int sc = w + sh; if (sc >= FSZ) sc -= FSZ;
#pragma unroll 4
    for (int h = h0; h < FSZ; h += 4) {
        int sr = h + sh; if (sr >= FSZ) sr -= FSZ;
        sm[h][w] = __ldg(xp + sr * FSZ + sc);
    }
    __syncthreads();

    bool wl = (w > 0), wr = (w < FSZ - 1);
#pragma unroll 4
    for (int h = h0; h < FSZ; h += 4) {
        float acc = 0.f;
        if (h > 0) {
            if (wl) acc += wt[0] * sm[h - 1][w - 1];
            acc += wt[1] * sm[h - 1][w];
            if (wr) acc += wt[2] * sm[h - 1][w + 1];
        }
        if (wl) acc += wt[3] * sm[h][w - 1];
        acc += wt[4] * sm[h][w];
        if (wr) acc += wt[5] * sm[h][w + 1];
        if (h < FSZ - 1) {
            if (wl) acc += wt[6] * sm[h + 1][w - 1];
            acc += wt[7] * sm[h + 1][w];
            if (wr) acc += wt[8] * sm[h + 1][w + 1];
        }
        yp[h * FSZ + w] = acc;
    }
}

// ---------------------------------------------------------------------------
// Tensor-core GEMM (tf32 mma.sync m16n8k8) with fused bias.
// C[M,N] = A[M,K] @ B[K,N] + bias[M]
// BM=BN=128, BK=16, 256 threads = 8 warps (4M x 2N), warp tile 32x64.
// Values rounded to tf32 once at smem-store time (cvt.rna).
// nchw=0: row-major store. nchw=1: scatter to NCHW (d_out).
// ---------------------------------------------------------------------------
#define BM 128
#define BN 128
#define BK 16
#define SP 136                     // smem row stride (floats); 136%32=8 -> conflict-free frags

__global__ __launch_bounds__(256) void tgemm_bias(
    const float* __restrict__ A, const float* __restrict__ B,
    const float* __restrict__ bias, float* __restrict__ Cout,
    int M, int N, int K, int nchw)
{
    __shared__ float As[2][BK * SP];   // [k][m]
    __shared__ float Bs[2][BK * SP];   // [k][n]

    int tid = threadIdx.x, lane = tid & 31, warp = tid >> 5;
    int lk = lane & 3, lm = lane >> 2;
    int wm = (warp >> 1) * 32, wn = (warp & 1) * 64;
    int bm = blockIdx.y * BM, bn = blockIdx.x * BN;

    float acc[2][8][4];
#pragma unroll
    for (int i = 0; i < 2; i++)
#pragma unroll
        for (int j = 0; j < 8; j++)
#pragma unroll
            for (int r = 0; r < 4; r++) acc[i][j][r] = 0.f;

    // global load assignments
    int arow = tid >> 1, acol = (tid & 1) * 8;        // A: row arow, cols acol..acol+7
    int brow = (tid >> 5) * 2, bcol = (tid & 31) * 4; // B: rows brow,brow+1, cols bcol..+3
    const float* Aptr = A + (size_t)(bm + arow) * K + acol;
    const float* Bptr = B + (size_t)brow * N + bn + bcol;

    float4 a0 = *(const float4*)(Aptr);
    float4 a1 = *(const float4*)(Aptr + 4);
    float4 b0 = *(const float4*)(Bptr);
    float4 b1 = *(const float4*)(Bptr + N);

#define STORE_CHUNK(bufi)                                                     \
    {                                                                         \
        float* pa = &As[bufi][0];                                             \
        pa[(acol + 0) * SP + arow] = to_tf32(a0.x);                           \
        pa[(acol + 1) * SP + arow] = to_tf32(a0.y);                           \
        pa[(acol + 2) * SP + arow] = to_tf32(a0.z);                           \
        pa[(acol + 3) * SP + arow] = to_tf32(a0.w);                           \
        pa[(acol + 4) * SP + arow] = to_tf32(a1.x);                           \
        pa[(acol + 5) * SP + arow] = to_tf32(a1.y);                           \
        pa[(acol + 6) * SP + arow] = to_tf32(a1.z);                           \
        pa[(acol + 7) * SP + arow] = to_tf32(a1.w);                           \
        float* pb = &Bs[bufi][0];                                             \
        pb[brow * SP + bcol + 0] = to_tf32(b0.x);                             \
        pb[brow * SP + bcol + 1] = to_tf32(b0.y);                             \
        pb[brow * SP + bcol + 2] = to_tf32(b0.z);                             \
        pb[brow * SP + bcol + 3] = to_tf32(b0.w);                             \
        pb[(brow + 1) * SP + bcol + 0] = to_tf32(b1.x);                       \
        pb[(brow + 1) * SP + bcol + 1] = to_tf32(b1.y);                       \
        pb[(brow + 1) * SP + bcol + 2] = to_tf32(b1.z);                       \
        pb[(brow + 1) * SP + bcol + 3] = to_tf32(b1.w);                       \
    }

    STORE_CHUNK(0)
    __syncthreads();

    int buf = 0;
    for (int k0g = 0; k0g < K; k0g += BK) {
        bool more = (k0g + BK) < K;
        if (more) {
            a0 = *(const float4*)(Aptr + k0g + BK);
            a1 = *(const float4*)(Aptr + k0g + BK + 4);
            b0 = *(const float4*)(Bptr + (size_t)(k0g + BK) * N);
            b1 = *(const float4*)(Bptr + (size_t)(k0g + BK + 1) * N);
        }
#pragma unroll
        for (int s = 0; s < 2; s++) {
            int k0 = s * 8;
            const float* pAk  = &As[buf][(k0 + lk) * SP];
            const float* pAk4 = &As[buf][(k0 + 4 + lk) * SP];
            const float* pBk  = &Bs[buf][(k0 + lk) * SP];
            const float* pBk4 = &Bs[buf][(k0 + 4 + lk) * SP];

            uint32_t af[2][4];
#pragma unroll
            for (int i = 0; i < 2; i++) {
                int m0 = wm + i * 16 + lm;
                af[i][0] = __float_as_uint(pAk[m0]);
                af[i][1] = __float_as_uint(pAk[m0 + 8]);
                af[i][2] = __float_as_uint(pAk4[m0]);
                af[i][3] = __float_as_uint(pAk4[m0 + 8]);
            }
#pragma unroll
            for (int j = 0; j < 8; j++) {
                int n0 = wn + j * 8 + lm;
                uint32_t bf0 = __float_as_uint(pBk[n0]);
                uint32_t bf1 = __float_as_uint(pBk4[n0]);
#pragma unroll
                for (int i = 0; i < 2; i++) {
                    asm volatile(
                        "mma.sync.aligned.m16n8k8.row.col.f32.tf32.tf32.f32 "
                        "{%0,%1,%2,%3}, {%4,%5,%6,%7}, {%8,%9}, {%0,%1,%2,%3};"
                        : "+f"(acc[i][j][0]), "+f"(acc[i][j][1]),
                          "+f"(acc[i][j][2]), "+f"(acc[i][j][3])
                        : "r"(af[i][0]), "r"(af[i][1]), "r"(af[i][2]), "r"(af[i][3]),
                          "r"(bf0), "r"(bf1));
                }
            }
        }
        if (more) {
            __syncthreads();
            buf ^= 1;
            STORE_CHUNK(buf)
            __syncthreads();
        }
    }

    // epilogue: d0->(m,n) d1->(m,n+1) d2->(m+8,n) d3->(m+8,n+1)
#pragma unroll
    for (int i = 0; i < 2; i++) {
        int m = bm + wm + i * 16 + lm;
        float bv0 = __ldg(&bias[m]);
        float bv1 = __ldg(&bias[m + 8]);
#pragma unroll
        for (int j = 0; j < 8; j++) {
            int n = bn + wn + j * 8 + 2 * lk;
            float v00 = acc[i][j][0] + bv0;
            float v01 = acc[i][j][1] + bv0;
            float v10 = acc[i][j][2] + bv1;
            float v11 = acc[i][j][3] + bv1;
            if (nchw) {
                int bidx = n / HWSZ, hw = n - bidx * HWSZ;
                size_t base0 = ((size_t)bidx * CCH + m) * HWSZ + hw;
                size_t base1 = ((size_t)bidx * CCH + m + 8) * HWSZ + hw;
                Cout[base0] = v00; Cout[base0 + 1] = v01;
                Cout[base1] = v10; Cout[base1 + 1] = v11;
            } else {
                size_t r0 = (size_t)m * N + n;
                size_t r1 = (size_t)(m + 8) * N + n;
                *(float2*)&Cout[r0] = make_float2(v00, v01);
                *(float2*)&Cout[r1] = make_float2(v10, v11);
            }
        }
    }
#undef STORE_CHUNK
}

// ---------------------------------------------------------------------------
// Windowed attention: one CTA per (batch, head, window).
// qkv layout: [ch][b][hw] (1152 x 50176). output: NCHW.
// bias[i,j] = pos_emb[xj-xi+6, yj-yi+6]   (rel = idx[j] - idx[i] + 6)
// ---------------------------------------------------------------------------
__global__ __launch_bounds__(256) void attn_kernel(
    const float* __restrict__ qkv, const float* __restrict__ pos_emb,
    float* __restrict__ out)
{
    const float DK = 0.17677669529663687f;  // 32^-0.5
    int blk = blockIdx.x;
    int wi = blk & 63;
    int head = (blk >> 6) % NHEADS;
    int b = blk / (64 * NHEADS);
    int wy = wi >> 3, wx = wi & 7;
    bool zm = (wy == 7);   // last window row -> zero_dim mask
    bool om = (wx == 7);   // last window col -> one_dim mask

    __shared__ float qs[49][33], ks[49][33], vs[49][33];
    __shared__ float dsh[49 * 49];
    __shared__ float pe[169];

    int tid = threadIdx.x;
    if (tid < 169) pe[tid] = pos_emb[tid];

    for (int t = tid; t < 49 * 32; t += 256) {
        int i = t >> 5, d = t & 31;
        int h = wy * 7 + i / 7, w = wx * 7 + i % 7;
        size_t base = (size_t)b * HWSZ + h * FSZ + w;
        int ch = head * HD + d;
        qs[i][d] = qkv[(size_t)ch * NTOK + base];
        ks[i][d] = qkv[(size_t)(ch + CCH) * NTOK + base];
        vs[i][d] = qkv[(size_t)(ch + 2 * CCH) * NTOK + base];
    }
    __syncthreads();

    for (int t = tid; t < 49 * 49; t += 256) {
        int i = t / 49, j = t - i * 49;
        float s = 0.f;
#pragma unroll
        for (int d = 0; d < 32; d++) s += qs[i][d] * ks[j][d];
        s *= DK;
        int xi = i / 7, yi = i - (i / 7) * 7;
        int xj = j / 7, yj = j - (j / 7) * 7;
        s += pe[(xj - xi + 6) * 13 + (yj - yi + 6)];   // rel = idx[j]-idx[i]+6
        bool masked = (zm && ((i >= 28) != (j >= 28))) ||
                      (om && ((yi >= 4) != (yj >= 4)));
        dsh[t] = masked ? -1e30f : s;
    }
    __syncthreads();

    if (tid < 49) {
        float mx = -1e30f;
#pragma unroll
        for (int j = 0; j < 49; j++) mx = fmaxf(mx, dsh[tid * 49 + j]);
        float sum = 0.f;
#pragma unroll
        for (int j = 0; j < 49; j++) {
            float e = __expf(dsh[tid * 49 + j] - mx);
            dsh[tid * 49 + j] = e;
            sum += e;
        }
        float inv = 1.f / sum;
#pragma unroll
        for (int j = 0; j < 49; j++) dsh[tid * 49 + j] *= inv;
    }
    __syncthreads();

    for (int t = tid; t < 49 * 32; t += 256) {
        int i = t >> 5, d = t & 31;
        float s = 0.f;
#pragma unroll
        for (int j = 0; j < 49; j++) s += dsh[i * 49 + j] * vs[j][d];
        int h = wy * 7 + i / 7, w = wx * 7 + i % 7;
        int ch = head * HD + d;
        out[((size_t)b * CCH + ch) * HWSZ + h * FSZ + w] = s;
    }
}

// ---------------------------------------------------------------------------
extern "C" void kernel_launch(void* const* d_in, const int* in_sizes, int n_in,
                              void* d_out, int out_size)
{
    const float* x       = (const float*)d_in[0];
    const float* qkv_dw  = (const float*)d_in[1];
    const float* qkv_pw  = (const float*)d_in[2];
    const float* qkv_pb  = (const float*)d_in[3];
    const float* out_dw  = (const float*)d_in[4];
    const float* out_pw  = (const float*)d_in[5];
    const float* out_pb  = (const float*)d_in[6];
    const float* pos_emb = (const float*)d_in[7];
    float* out = (float*)d_out;

    float* ybuf; cudaGetSymbolAddress((void**)&ybuf, g_ybuf);
    float* qkvb; cudaGetSymbolAddress((void**)&qkvb, g_qkv);
    float* attb; cudaGetSymbolAddress((void**)&attb, g_attn);

    // 1. roll(-3,-3) + dwconv3x3  -> [c][b][hw]
    dwconv_kernel<<<BATCH * CCH, 224>>>(x, qkv_dw, ybuf, 3);
    // 2. qkv pointwise: [1152,384] @ [384,50176] + bias (tf32 tensor cores)
    tgemm_bias<<<dim3(NTOK / BN, 3 * CCH / BM), 256>>>(
        qkv_pw, ybuf, qkv_pb, qkvb, 3 * CCH, NTOK, CCH, 0);
    // 3. windowed attention -> NCHW
    attn_kernel<<<BATCH * NHEADS * 64, 256>>>(qkvb, pos_emb, attb);
    // 4. roll(+3,+3) + dwconv3x3 -> [c][b][hw]
    dwconv_kernel<<<BATCH * CCH, 224>>>(attb, out_dw, ybuf, 53);
    // 5. output pointwise: [384,384] @ [384,50176] + bias -> NCHW d_out
    tgemm_bias<<<dim3(NTOK / BN, CCH / BM), 256>>>(
        out_pw, ybuf, out_pb, out, CCH, NTOK, CCH, 1);
}

// round 11
// speedup vs baseline: 1.7944x; 1.0698x over previous
#include <cuda_runtime.h>
#include <cstdint>

#define CCH    384
#define NHEADS 12
#define HD     32
#define FSZ    56
#define HWSZ   3136          // 56*56
#define BATCH  16
#define NTOK   (BATCH*HWSZ)  // 50176
#define QKVC   (3*CCH)       // 1152

// ---------------- scratch (device globals; no cudaMalloc allowed) ----------
__device__ float g_ybuf[CCH * NTOK];          //  77 MB: dwconv output, [c][b][hw]
__device__ float g_qkv [QKVC * NTOK];         // 231 MB: qkvT, [tok][ch]
__device__ float g_attn[BATCH * CCH * HWSZ];  //  77 MB: attention output, NCHW

__device__ __forceinline__ float to_tf32(float x) {
    float y;
    asm("cvt.rna.tf32.f32 %0, %1;" : "=f"(y) : "f"(x));
    return y;
}

// ---------------------------------------------------------------------------
// Fused roll + depthwise 3x3 conv (pad 1), smem-tiled, 224 threads (1 col/thr).
// input: NCHW. output: [c][b][hw].
// sh=3 implements roll(-3) before conv; sh=53 implements roll(+3).
// ---------------------------------------------------------------------------
__global__ __launch_bounds__(224) void dwconv_kernel(
    const float* __restrict__ x, const float* __restrict__ wgt,
    float* __restrict__ y, int sh)
{
    __shared__ float sm[FSZ][FSZ + 1];
    int bc = blockIdx.x;           // b*CCH + c
    int b = bc / CCH, c = bc % CCH;
    float wt[9];
#pragma unroll
    for (int i = 0; i < 9; i++) wt[i] = __ldg(&wgt[c * 9 + i]);
    const float* xp = x + (size_t)bc * HWSZ;
    float*       yp = y + ((size_t)c * BATCH + b) * HWSZ;

    int tid = threadIdx.x;
    int w = tid % FSZ, h0 = tid / FSZ;      // 224 = 4 rows x 56 cols
    int sc = w + sh; if (sc >= FSZ) sc -= FSZ;
#pragma unroll 4
    for (int h = h0; h < FSZ; h += 4) {
        int sr = h + sh; if (sr >= FSZ) sr -= FSZ;
        sm[h][w] = __ldg(xp + sr * FSZ + sc);
    }
    __syncthreads();

    bool wl = (w > 0), wr = (w < FSZ - 1);
#pragma unroll 4
    for (int h = h0; h < FSZ; h += 4) {
        float acc = 0.f;
        if (h > 0) {
            if (wl) acc += wt[0] * sm[h - 1][w - 1];
            acc += wt[1] * sm[h - 1][w];
            if (wr) acc += wt[2] * sm[h - 1][w + 1];
        }
        if (wl) acc += wt[3] * sm[h][w - 1];
        acc += wt[4] * sm[h][w];
        if (wr) acc += wt[5] * sm[h][w + 1];
        if (h < FSZ - 1) {
            if (wl) acc += wt[6] * sm[h + 1][w - 1];
            acc += wt[7] * sm[h + 1][w];
            if (wr) acc += wt[8] * sm[h + 1][w + 1];
        }
        yp[h * FSZ + w] = acc;
    }
}

// ---------------------------------------------------------------------------
// Tensor-core GEMM (tf32 mma.sync m16n8k8) with fused bias.
// C[M,N] = A[M,K] @ B[K,N] + bias[M]
// BM=BN=128, BK=16, 256 threads = 8 warps (4M x 2N), warp tile 32x64.
// mode 0: row-major [M][N].  mode 1: NCHW scatter (d_out).
// mode 2: transposed [N][M] (qkvT for attention).
// ---------------------------------------------------------------------------
#define BM 128
#define BN 128
#define BK 16
#define SP 136                     // smem row stride (floats); 136%32=8 -> conflict-free frags

__global__ __launch_bounds__(256) void tgemm_bias(
    const float* __restrict__ A, const float* __restrict__ B,
    const float* __restrict__ bias, float* __restrict__ Cout,
    int M, int N, int K, int mode)
{
    __shared__ float As[2][BK * SP];   // [k][m]
    __shared__ float Bs[2][BK * SP];   // [k][n]

    int tid = threadIdx.x, lane = tid & 31, warp = tid >> 5;
    int lk = lane & 3, lm = lane >> 2;
    int wm = (warp >> 1) * 32, wn = (warp & 1) * 64;
    int bm = blockIdx.y * BM, bn = blockIdx.x * BN;

    float acc[2][8][4];
#pragma unroll
    for (int i = 0; i < 2; i++)
#pragma unroll
        for (int j = 0; j < 8; j++)
#pragma unroll
            for (int r = 0; r < 4; r++) acc[i][j][r] = 0.f;

    // global load assignments
    int arow = tid >> 1, acol = (tid & 1) * 8;        // A: row arow, cols acol..acol+7
    int brow = (tid >> 5) * 2, bcol = (tid & 31) * 4; // B: rows brow,brow+1, cols bcol..+3
    const float* Aptr = A + (size_t)(bm + arow) * K + acol;
    const float* Bptr = B + (size_t)brow * N + bn + bcol;

    float4 a0 = *(const float4*)(Aptr);
    float4 a1 = *(const float4*)(Aptr + 4);
    float4 b0 = *(const float4*)(Bptr);
    float4 b1 = *(const float4*)(Bptr + N);

#define STORE_CHUNK(bufi)                                                     \
    {                                                                         \
        float* pa = &As[bufi][0];                                             \
        pa[(acol + 0) * SP + arow] = to_tf32(a0.x);                           \
        pa[(acol + 1) * SP + arow] = to_tf32(a0.y);                           \
        pa[(acol + 2) * SP + arow] = to_tf32(a0.z);                           \
        pa[(acol + 3) * SP + arow] = to_tf32(a0.w);                           \
        pa[(acol + 4) * SP + arow] = to_tf32(a1.x);                           \
        pa[(acol + 5) * SP + arow] = to_tf32(a1.y);                           \
        pa[(acol + 6) * SP + arow] = to_tf32(a1.z);                           \
        pa[(acol + 7) * SP + arow] = to_tf32(a1.w);                           \
        float* pb = &Bs[bufi][0];                                             \
        pb[brow * SP + bcol + 0] = to_tf32(b0.x);                             \
        pb[brow * SP + bcol + 1] = to_tf32(b0.y);                             \
        pb[brow * SP + bcol + 2] = to_tf32(b0.z);                             \
        pb[brow * SP + bcol + 3] = to_tf32(b0.w);                             \
        pb[(brow + 1) * SP + bcol + 0] = to_tf32(b1.x);                       \
        pb[(brow + 1) * SP + bcol + 1] = to_tf32(b1.y);                       \
        pb[(brow + 1) * SP + bcol + 2] = to_tf32(b1.z);                       \
        pb[(brow + 1) * SP + bcol + 3] = to_tf32(b1.w);                       \
    }

    STORE_CHUNK(0)
    __syncthreads();

    int buf = 0;
    for (int k0g = 0; k0g < K; k0g += BK) {
        bool more = (k0g + BK) < K;
        if (more) {
            a0 = *(const float4*)(Aptr + k0g + BK);
            a1 = *(const float4*)(Aptr + k0g + BK + 4);
            b0 = *(const float4*)(Bptr + (size_t)(k0g + BK) * N);
            b1 = *(const float4*)(Bptr + (size_t)(k0g + BK + 1) * N);
        }
#pragma unroll
        for (int s = 0; s < 2; s++) {
            int k0 = s * 8;
            const float* pAk  = &As[buf][(k0 + lk) * SP];
            const float* pAk4 = &As[buf][(k0 + 4 + lk) * SP];
            const float* pBk  = &Bs[buf][(k0 + lk) * SP];
            const float* pBk4 = &Bs[buf][(k0 + 4 + lk) * SP];

            uint32_t af[2][4];
#pragma unroll
            for (int i = 0; i < 2; i++) {
                int m0 = wm + i * 16 + lm;
                af[i][0] = __float_as_uint(pAk[m0]);
                af[i][1] = __float_as_uint(pAk[m0 + 8]);
                af[i][2] = __float_as_uint(pAk4[m0]);
                af[i][3] = __float_as_uint(pAk4[m0 + 8]);
            }
#pragma unroll
            for (int j = 0; j < 8; j++) {
                int n0 = wn + j * 8 + lm;
                uint32_t bf0 = __float_as_uint(pBk[n0]);
                uint32_t bf1 = __float_as_uint(pBk4[n0]);
#pragma unroll
                for (int i = 0; i < 2; i++) {
                    asm volatile(
                        "mma.sync.aligned.m16n8k8.row.col.f32.tf32.tf32.f32 "
                        "{%0,%1,%2,%3}, {%4,%5,%6,%7}, {%8,%9}, {%0,%1,%2,%3};"
                        : "+f"(acc[i][j][0]), "+f"(acc[i][j][1]),
                          "+f"(acc[i][j][2]), "+f"(acc[i][j][3])
                        : "r"(af[i][0]), "r"(af[i][1]), "r"(af[i][2]), "r"(af[i][3]),
                          "r"(bf0), "r"(bf1));
                }
            }
        }
        if (more) {
            __syncthreads();
            buf ^= 1;
            STORE_CHUNK(buf)
            __syncthreads();
        }
    }

    // epilogue: d0->(m,n) d1->(m,n+1) d2->(m+8,n) d3->(m+8,n+1)
#pragma unroll
    for (int i = 0; i < 2; i++) {
        int m = bm + wm + i * 16 + lm;
        float bv0 = __ldg(&bias[m]);
        float bv1 = __ldg(&bias[m + 8]);
#pragma unroll
        for (int j = 0; j < 8; j++) {
            int n = bn + wn + j * 8 + 2 * lk;
            float v00 = acc[i][j][0] + bv0;
            float v01 = acc[i][j][1] + bv0;
            float v10 = acc[i][j][2] + bv1;
            float v11 = acc[i][j][3] + bv1;
            if (mode == 1) {
                int bidx = n / HWSZ, hw = n - bidx * HWSZ;
                size_t base0 = ((size_t)bidx * CCH + m) * HWSZ + hw;
                size_t base1 = ((size_t)bidx * CCH + m + 8) * HWSZ + hw;
                Cout[base0] = v00; Cout[base0 + 1] = v01;
                Cout[base1] = v10; Cout[base1 + 1] = v11;
            } else if (mode == 2) {
                // transposed: Cout[n][m], row stride M
                size_t r0 = (size_t)n * M + m;
                size_t r1 = (size_t)(n + 1) * M + m;
                Cout[r0] = v00;     Cout[r0 + 8] = v10;
                Cout[r1] = v01;     Cout[r1 + 8] = v11;
            } else {
                size_t r0 = (size_t)m * N + n;
                size_t r1 = (size_t)(m + 8) * N + n;
                *(float2*)&Cout[r0] = make_float2(v00, v01);
                *(float2*)&Cout[r1] = make_float2(v10, v11);
            }
        }
    }
#undef STORE_CHUNK
}

// ---------------------------------------------------------------------------
// Windowed attention: one CTA per (batch, head, window).
// qkvT layout: [tok][ch] (50176 x 1152) -> fully coalesced loads.
// output: NCHW, written d-major (contiguous window rows).
// bias[i,j] = pos_emb[xj-xi+6, yj-yi+6]   (rel = idx[j] - idx[i] + 6)
// ---------------------------------------------------------------------------
__global__ __launch_bounds__(256) void attn_kernel(
    const float* __restrict__ qkvT, const float* __restrict__ pos_emb,
    float* __restrict__ out)
{
    const float DK = 0.17677669529663687f;  // 32^-0.5
    int blk = blockIdx.x;
    int wi = blk & 63;
    int head = (blk >> 6) % NHEADS;
    int b = blk / (64 * NHEADS);
    int wy = wi >> 3, wx = wi & 7;
    bool zm = (wy == 7);   // last window row -> zero_dim mask
    bool om = (wx == 7);   // last window col -> one_dim mask

    __shared__ float qs[49][33], ks[49][33], vs[49][33];
    __shared__ float dsh[49 * 49];
    __shared__ float pe[169];

    int tid = threadIdx.x;
    if (tid < 169) pe[tid] = pos_emb[tid];

    // coalesced loads: token i -> 32 consecutive ch
    int qoff = head * HD;
    for (int t = tid; t < 49 * 32; t += 256) {
        int i = t >> 5, d = t & 31;
        int h = wy * 7 + i / 7, w = wx * 7 + i % 7;
        size_t tok = (size_t)b * HWSZ + h * FSZ + w;
        const float* p = qkvT + tok * QKVC + qoff + d;
        qs[i][d] = p[0];
        ks[i][d] = p[CCH];
        vs[i][d] = p[2 * CCH];
    }
    __syncthreads();

    // dots + bias + mask
    for (int t = tid; t < 49 * 49; t += 256) {
        int i = t / 49, j = t - i * 49;
        float s = 0.f;
#pragma unroll
        for (int d = 0; d < 32; d++) s += qs[i][d] * ks[j][d];
        s *= DK;
        int xi = i / 7, yi = i - (i / 7) * 7;
        int xj = j / 7, yj = j - (j / 7) * 7;
        s += pe[(xj - xi + 6) * 13 + (yj - yi + 6)];   // rel = idx[j]-idx[i]+6
        bool masked = (zm && ((i >= 28) != (j >= 28))) ||
                      (om && ((yi >= 4) != (yj >= 4)));
        dsh[t] = masked ? -1e30f : s;
    }
    __syncthreads();

    // quad-parallel softmax: 4 lanes per row, rows 0..48 (threads 0..195).
    // 196 = 49 complete quads; shuffles use the quad-local mask so every
    // named lane participates (full-warp mask here would deadlock warp 6,
    // whose lanes 4..31 are outside the branch).
    if (tid < 196) {
        int row = tid >> 2, sub = tid & 3;
        unsigned qmask = 0xFu << (tid & 28);   // this quad's 4 lanes
        float* rp = &dsh[row * 49];
        float mx = -1e30f;
        for (int j = sub; j < 49; j += 4) mx = fmaxf(mx, rp[j]);
        mx = fmaxf(mx, __shfl_xor_sync(qmask, mx, 1));
        mx = fmaxf(mx, __shfl_xor_sync(qmask, mx, 2));
        float sum = 0.f;
        for (int j = sub; j < 49; j += 4) {
            float e = __expf(rp[j] - mx);
            rp[j] = e;
            sum += e;
        }
        sum += __shfl_xor_sync(qmask, sum, 1);
        sum += __shfl_xor_sync(qmask, sum, 2);
        float inv = 1.f / sum;
        for (int j = sub; j < 49; j += 4) rp[j] *= inv;
    }
    __syncthreads();

    // out = attn @ v, d-major write: consecutive threads sweep tokens
    for (int t = tid; t < 49 * 32; t += 256) {
        int d = t / 49, i = t - d * 49;
        float s = 0.f;
#pragma unroll
        for (int j = 0; j < 49; j++) s += dsh[i * 49 + j] * vs[j][d];
        int h = wy * 7 + i / 7, w = wx * 7 + i % 7;
        int ch = head * HD + d;
        out[((size_t)b * CCH + ch) * HWSZ + h * FSZ + w] = s;
    }
}

// ---------------------------------------------------------------------------
extern "C" void kernel_launch(void* const* d_in, const int* in_sizes, int n_in,
                              void* d_out, int out_size)
{
    const float* x       = (const float*)d_in[0];
    const float* qkv_dw  = (const float*)d_in[1];
    const float* qkv_pw  = (const float*)d_in[2];
    const float* qkv_pb  = (const float*)d_in[3];
    const float* out_dw  = (const float*)d_in[4];
    const float* out_pw  = (const float*)d_in[5];
    const float* out_pb  = (const float*)d_in[6];
    const float* pos_emb = (const float*)d_in[7];
    float* out = (float*)d_out;

    float* ybuf; cudaGetSymbolAddress((void**)&ybuf, g_ybuf);
    float* qkvb; cudaGetSymbolAddress((void**)&qkvb, g_qkv);
    float* attb; cudaGetSymbolAddress((void**)&attb, g_attn);

    // 1. roll(-3,-3) + dwconv3x3  -> [c][b][hw]
    dwconv_kernel<<<BATCH * CCH, 224>>>(x, qkv_dw, ybuf, 3);
    // 2. qkv pointwise -> TRANSPOSED qkvT [tok][ch] (mode 2)
    tgemm_bias<<<dim3(NTOK / BN, QKVC / BM), 256>>>(
        qkv_pw, ybuf, qkv_pb, qkvb, QKVC, NTOK, CCH, 2);
    // 3. windowed attention -> NCHW
    attn_kernel<<<BATCH * NHEADS * 64, 256>>>(qkvb, pos_emb, attb);
    // 4. roll(+3,+3) + dwconv3x3 -> [c][b][hw]
    dwconv_kernel<<<BATCH * CCH, 224>>>(attb, out_dw, ybuf, 53);
    // 5. output pointwise: [384,384] @ [384,50176] + bias -> NCHW d_out
    tgemm_bias<<<dim3(NTOK / BN, CCH / BM), 256>>>(
        out_pw, ybuf, out_pb, out, CCH, NTOK, CCH, 1);
}

// round 13
// speedup vs baseline: 1.9787x; 1.1027x over previous
#include <cuda_runtime.h>
#include <cstdint>

#define CCH    384
#define NHEADS 12
#define HD     32
#define FSZ    56
#define HWSZ   3136          // 56*56
#define BATCH  16
#define NTOK   (BATCH*HWSZ)  // 50176
#define QKVC   (3*CCH)       // 1152

// ---------------- scratch (device globals; no cudaMalloc allowed) ----------
__device__ float g_ybuf[CCH * NTOK];          //  77 MB: dwconv output, [c][b][hw]
__device__ float g_qkv [QKVC * NTOK];         // 231 MB: qkvT, [tok][ch]
__device__ float g_attn[BATCH * CCH * HWSZ];  //  77 MB: attention output, NCHW

__device__ __forceinline__ float to_tf32(float x) {
    float y;
    asm("cvt.rna.tf32.f32 %0, %1;" : "=f"(y) : "f"(x));
    return y;
}
__device__ __forceinline__ uint32_t tf32_bits(float x) {
    return __float_as_uint(to_tf32(x));
}
__device__ __forceinline__ void cp_async16(void* smem_dst, const void* gsrc) {
    uint32_t s = (uint32_t)__cvta_generic_to_shared(smem_dst);
    asm volatile("cp.async.cg.shared.global [%0], [%1], 16;\n" :: "r"(s), "l"(gsrc));
}

// ncu window marker: makes launch #6 = gemm2 instead of dwconv (-s 5 -c 1).
__global__ void marker_kernel() {}

// ---------------------------------------------------------------------------
// Fused roll + depthwise 3x3 conv (pad 1), smem-tiled, 224 threads.
// input: NCHW. output: [c][b][hw]. sh=3: roll(-3); sh=53: roll(+3).
// ---------------------------------------------------------------------------
__global__ __launch_bounds__(224) void dwconv_kernel(
    const float* __restrict__ x, const float* __restrict__ wgt,
    float* __restrict__ y, int sh)
{
    __shared__ float sm[FSZ][FSZ + 1];
    int bc = blockIdx.x;           // b*CCH + c
    int b = bc / CCH, c = bc % CCH;
    float wt[9];
#pragma unroll
    for (int i = 0; i < 9; i++) wt[i] = __ldg(&wgt[c * 9 + i]);
    const float* xp = x + (size_t)bc * HWSZ;
    float*       yp = y + ((size_t)c * BATCH + b) * HWSZ;

    int tid = threadIdx.x;
    int w = tid % FSZ, h0 = tid / FSZ;      // 224 = 4 rows x 56 cols
    int sc = w + sh; if (sc >= FSZ) sc -= FSZ;
#pragma unroll 4
    for (int h = h0; h < FSZ; h += 4) {
        int sr = h + sh; if (sr >= FSZ) sr -= FSZ;
        sm[h][w] = __ldg(xp + sr * FSZ + sc);
    }
    __syncthreads();

    bool wl = (w > 0), wr = (w < FSZ - 1);
#pragma unroll 4
    for (int h = h0; h < FSZ; h += 4) {
        float acc = 0.f;
        if (h > 0) {
            if (wl) acc += wt[0] * sm[h - 1][w - 1];
            acc += wt[1] * sm[h - 1][w];
            if (wr) acc += wt[2] * sm[h - 1][w + 1];
        }
        if (wl) acc += wt[3] * sm[h][w - 1];
        acc += wt[4] * sm[h][w];
        if (wr) acc += wt[5] * sm[h][w + 1];
        if (h < FSZ - 1) {
            if (wl) acc += wt[6] * sm[h + 1][w - 1];
            acc += wt[7] * sm[h + 1][w];
            if (wr) acc += wt[8] * sm[h + 1][w + 1];
        }
        yp[h * FSZ + w] = acc;
    }
}

// ---------------------------------------------------------------------------
// Tensor-core GEMM (tf32 mma.sync m16n8k8), cp.async 2-stage, BK=32.
// C[M,N] = A[M,K] @ B[K,N] + bias[M]
// BM=BN=128, 256 threads = 8 warps (4M x 2N), warp tile 32x64.
// Smem: As[2][128][36] raw fp32 (m-major), Bs[2][32][136] raw fp32 (k-major).
// tf32 cvt.rna applied at fragment-load time (same math as round-5/11).
// mode 0: row-major. mode 1: NCHW scatter. mode 2: transposed [N][M].
// ---------------------------------------------------------------------------
#define BM 128
#define BN 128
#define BK 32
#define SPA 36     // As row stride: (lm*4+lk) mod 32 distinct -> conflict-free
#define SPB 136    // Bs row stride: (lk*8+lm) mod 32 distinct -> conflict-free
#define ASZ (BM * SPA)   // 4608 floats
#define BSZ (BK * SPB)   // 4352 floats
#define GEMM_SMEM ((2 * (ASZ + BSZ)) * 4)   // 71680 bytes

__global__ __launch_bounds__(256) void tgemm_bias(
    const float* __restrict__ A, const float* __restrict__ B,
    const float* __restrict__ bias, float* __restrict__ Cout,
    int M, int N, int K, int mode)
{
    extern __shared__ float smem[];
    float* As = smem;                 // [2][ASZ]
    float* Bs = smem + 2 * ASZ;       // [2][BSZ]

    int tid = threadIdx.x, lane = tid & 31, warp = tid >> 5;
    int lk = lane & 3, lm = lane >> 2;
    int wm = (warp >> 1) * 32, wn = (warp & 1) * 64;
    int bm = blockIdx.y * BM, bn = blockIdx.x * BN;

    float acc[2][8][4];
#pragma unroll
    for (int i = 0; i < 2; i++)
#pragma unroll
        for (int j = 0; j < 8; j++)
#pragma unroll
            for (int r = 0; r < 4; r++) acc[i][j][r] = 0.f;

    // cp.async tile issue: A 128x32 and B 32x128, each 1024 16B-chunks,
    // 4 chunks per thread (bijections over both tiles).
#define ISSUE_TILE(tile, bufi)                                                \
    {                                                                         \
        int k0g = (tile) * BK;                                                \
        float* abuf = As + (bufi) * ASZ;                                      \
        float* bbuf = Bs + (bufi) * BSZ;                                      \
        _Pragma("unroll")                                                     \
        for (int q = 0; q < 4; q++) {                                         \
            int c = tid + 256 * q;                                            \
            int ar = c >> 3, aoff = (c & 7) * 4;                              \
            cp_async16(abuf + ar * SPA + aoff,                                \
                       A + (size_t)(bm + ar) * K + k0g + aoff);               \
        }                                                                     \
        _Pragma("unroll")                                                     \
        for (int q = 0; q < 4; q++) {                                         \
            int c = tid + 256 * q;                                            \
            int br = c >> 5, bcf = (c & 31) * 4;                              \
            cp_async16(bbuf + br * SPB + bcf,                                 \
                       B + (size_t)(k0g + br) * N + bn + bcf);                \
        }                                                                     \
        asm volatile("cp.async.commit_group;\n" ::: "memory");                \
    }

    int nIter = K / BK;                // 12 for K=384
    ISSUE_TILE(0, 0)
    ISSUE_TILE(1, 1)

    for (int it = 0; it < nIter; it++) {
        if (it + 1 < nIter)
            asm volatile("cp.async.wait_group 1;\n" ::: "memory");
        else
            asm volatile("cp.async.wait_group 0;\n" ::: "memory");
        __syncthreads();

        int buf = it & 1;
        const float* abuf = As + buf * ASZ;
        const float* bbuf = Bs + buf * BSZ;
#pragma unroll
        for (int s = 0; s < 4; s++) {
            int k0 = s * 8;
            uint32_t af[2][4];
#pragma unroll
            for (int i = 0; i < 2; i++) {
                const float* pa = abuf + (wm + i * 16 + lm) * SPA + k0 + lk;
                af[i][0] = tf32_bits(pa[0]);
                af[i][1] = tf32_bits(pa[8 * SPA]);
                af[i][2] = tf32_bits(pa[4]);
                af[i][3] = tf32_bits(pa[8 * SPA + 4]);
            }
            const float* pb0 = bbuf + (k0 + lk) * SPB + wn + lm;
            const float* pb4 = pb0 + 4 * SPB;
#pragma unroll
            for (int j = 0; j < 8; j++) {
                uint32_t bf0 = tf32_bits(pb0[j * 8]);
                uint32_t bf1 = tf32_bits(pb4[j * 8]);
#pragma unroll
                for (int i = 0; i < 2; i++) {
                    asm volatile(
                        "mma.sync.aligned.m16n8k8.row.col.f32.tf32.tf32.f32 "
                        "{%0,%1,%2,%3}, {%4,%5,%6,%7}, {%8,%9}, {%0,%1,%2,%3};"
                        : "+f"(acc[i][j][0]), "+f"(acc[i][j][1]),
                          "+f"(acc[i][j][2]), "+f"(acc[i][j][3])
                        : "r"(af[i][0]), "r"(af[i][1]), "r"(af[i][2]), "r"(af[i][3]),
                          "r"(bf0), "r"(bf1));
                }
            }
        }
        __syncthreads();               // all reads done before refilling buf
        if (it + 2 < nIter)
            ISSUE_TILE(it + 2, buf)
    }
#undef ISSUE_TILE

    // epilogue: d0->(m,n) d1->(m,n+1) d2->(m+8,n) d3->(m+8,n+1)
#pragma unroll
    for (int i = 0; i < 2; i++) {
        int m = bm + wm + i * 16 + lm;
        float bv0 = __ldg(&bias[m]);
        float bv1 = __ldg(&bias[m + 8]);
#pragma unroll
        for (int j = 0; j < 8; j++) {
            int n = bn + wn + j * 8 + 2 * lk;
            float v00 = acc[i][j][0] + bv0;
            float v01 = acc[i][j][1] + bv0;
            float v10 = acc[i][j][2] + bv1;
            float v11 = acc[i][j][3] + bv1;
            if (mode == 1) {
                int bidx = n / HWSZ, hw = n - bidx * HWSZ;
                size_t base0 = ((size_t)bidx * CCH + m) * HWSZ + hw;
                size_t base1 = ((size_t)bidx * CCH + m + 8) * HWSZ + hw;
                Cout[base0] = v00; Cout[base0 + 1] = v01;
                Cout[base1] = v10; Cout[base1 + 1] = v11;
            } else if (mode == 2) {
                size_t r0 = (size_t)n * M + m;
                size_t r1 = (size_t)(n + 1) * M + m;
                Cout[r0] = v00;     Cout[r0 + 8] = v10;
                Cout[r1] = v01;     Cout[r1 + 8] = v11;
            } else {
                size_t r0 = (size_t)m * N + n;
                size_t r1 = (size_t)(m + 8) * N + n;
                *(float2*)&Cout[r0] = make_float2(v00, v01);
                *(float2*)&Cout[r1] = make_float2(v10, v11);
            }
        }
    }
}

// ---------------------------------------------------------------------------
// Windowed attention: one CTA per (batch, head, window).
// qkvT layout: [tok][ch] (50176 x 1152), coalesced. output: NCHW d-major.
// bias[i,j] = pos_emb[xj-xi+6, yj-yi+6]
// ---------------------------------------------------------------------------
__global__ __launch_bounds__(256) void attn_kernel(
    const float* __restrict__ qkvT, const float* __restrict__ pos_emb,
    float* __restrict__ out)
{
    const float DK = 0.17677669529663687f;  // 32^-0.5
    int blk = blockIdx.x;
    int wi = blk & 63;
    int head = (blk >> 6) % NHEADS;
    int b = blk / (64 * NHEADS);
    int wy = wi >> 3, wx = wi & 7;
    bool zm = (wy == 7);
    bool om = (wx == 7);

    __shared__ float qs[49][33], ks[49][33], vs[49][33];
    __shared__ float dsh[49 * 49];
    __shared__ float pe[169];

    int tid = threadIdx.x;
    if (tid < 169) pe[tid] = pos_emb[tid];

    int qoff = head * HD;
    for (int t = tid; t < 49 * 32; t += 256) {
        int i = t >> 5, d = t & 31;
        int h = wy * 7 + i / 7, w = wx * 7 + i % 7;
        size_t tok = (size_t)b * HWSZ + h * FSZ + w;
        const float* p = qkvT + tok * QKVC + qoff + d;
        qs[i][d] = p[0];
        ks[i][d] = p[CCH];
        vs[i][d] = p[2 * CCH];
    }
    __syncthreads();

    for (int t = tid; t < 49 * 49; t += 256) {
        int i = t / 49, j = t - i * 49;
        float s = 0.f;
#pragma unroll
        for (int d = 0; d < 32; d++) s += qs[i][d] * ks[j][d];
        s *= DK;
        int xi = i / 7, yi = i - (i / 7) * 7;
        int xj = j / 7, yj = j - (j / 7) * 7;
        s += pe[(xj - xi + 6) * 13 + (yj - yi + 6)];
        bool masked = (zm && ((i >= 28) != (j >= 28))) ||
                      (om && ((yi >= 4) != (yj >= 4)));
        dsh[t] = masked ? -1e30f : s;
    }
    __syncthreads();

    // quad-parallel softmax: threads 0..195 = 49 complete quads; quad-local
    // shuffle mask (full-warp mask would deadlock warp 6).
    if (tid < 196) {
        int row = tid >> 2, sub = tid & 3;
        unsigned qmask = 0xFu << (tid & 28);
        float* rp = &dsh[row * 49];
        float mx = -1e30f;
        for (int j = sub; j < 49; j += 4) mx = fmaxf(mx, rp[j]);
        mx = fmaxf(mx, __shfl_xor_sync(qmask, mx, 1));
        mx = fmaxf(mx, __shfl_xor_sync(qmask, mx, 2));
        float sum = 0.f;
        for (int j = sub; j < 49; j += 4) {
            float e = __expf(rp[j] - mx);
            rp[j] = e;
            sum += e;
        }
        sum += __shfl_xor_sync(qmask, sum, 1);
        sum += __shfl_xor_sync(qmask, sum, 2);
        float inv = 1.f / sum;
        for (int j = sub; j < 49; j += 4) rp[j] *= inv;
    }
    __syncthreads();

    for (int t = tid; t < 49 * 32; t += 256) {
        int d = t / 49, i = t - d * 49;
        float s = 0.f;
#pragma unroll
        for (int j = 0; j < 49; j++) s += dsh[i * 49 + j] * vs[j][d];
        int h = wy * 7 + i / 7, w = wx * 7 + i % 7;
        int ch = head * HD + d;
        out[((size_t)b * CCH + ch) * HWSZ + h * FSZ + w] = s;
    }
}

// ---------------------------------------------------------------------------
extern "C" void kernel_launch(void* const* d_in, const int* in_sizes, int n_in,
                              void* d_out, int out_size)
{
    const float* x       = (const float*)d_in[0];
    const float* qkv_dw  = (const float*)d_in[1];
    const float* qkv_pw  = (const float*)d_in[2];
    const float* qkv_pb  = (const float*)d_in[3];
    const float* out_dw  = (const float*)d_in[4];
    const float* out_pw  = (const float*)d_in[5];
    const float* out_pb  = (const float*)d_in[6];
    const float* pos_emb = (const float*)d_in[7];
    float* out = (float*)d_out;

    float* ybuf; cudaGetSymbolAddress((void**)&ybuf, g_ybuf);
    float* qkvb; cudaGetSymbolAddress((void**)&qkvb, g_qkv);
    float* attb; cudaGetSymbolAddress((void**)&attb, g_attn);

    cudaFuncSetAttribute(tgemm_bias,
        cudaFuncAttributeMaxDynamicSharedMemorySize, GEMM_SMEM);

    // 1. roll(-3,-3) + dwconv3x3  -> [c][b][hw]
    dwconv_kernel<<<BATCH * CCH, 224>>>(x, qkv_dw, ybuf, 3);
    // 1b. ncu marker: shifts the -s 5 -c 1 window onto gemm2
    marker_kernel<<<1, 1>>>();
    // 2. qkv pointwise -> TRANSPOSED qkvT [tok][ch] (mode 2)
    tgemm_bias<<<dim3(NTOK / BN, QKVC / BM), 256, GEMM_SMEM>>>(
        qkv_pw, ybuf, qkv_pb, qkvb, QKVC, NTOK, CCH, 2);
    // 3. windowed attention -> NCHW
    attn_kernel<<<BATCH * NHEADS * 64, 256>>>(qkvb, pos_emb, attb);
    // 4. roll(+3,+3) + dwconv3x3 -> [c][b][hw]
    dwconv_kernel<<<BATCH * CCH, 224>>>(attb, out_dw, ybuf, 53);
    // 5. output pointwise -> NCHW d_out (mode 1)
    tgemm_bias<<<dim3(NTOK / BN, CCH / BM), 256, GEMM_SMEM>>>(
        out_pw, ybuf, out_pb, out, CCH, NTOK, CCH, 1);
}